// round 6
// baseline (speedup 1.0000x reference)
#include <cuda_runtime.h>
#include <cstdint>

// ---------------------------------------------------------------------------
// NeuralCA: 40 steps of  x = clip(x + MLP(conv3x3(x)), 0, 1)
// B=4, CH=16, H=W=224, perception 48ch, hidden 128.
// Pair-split: each pixel handled by a thread PAIR (channel halves) to cut
// register pressure (~222 -> ~120) and double occupancy (8 -> 16 warps/SM).
// 512 thr/CTA = 256 pixels, packed-f32x2 weights in SMEM, activation
// exchange via spare SMEM, ping-pong device buffers, 40 launches.
// ---------------------------------------------------------------------------

#define BV     4
#define CHN    16
#define HH     224
#define WW     224
#define HWSZ   (HH * WW)
#define NSTEPS 40
#define NPIX   (BV * HWSZ)            // 200704
#define NTHR   512
#define PIXPB  256
#define NBLK   (NPIX / PIXPB)         // 784

typedef unsigned long long ull;

// packed-weight layout (float2 units == ull slots)
#define OFF_WP 0
#define N_WP   (16 * 9 * 24)          // conv: [ic][tap][oc_pair]   = 3456
#define OFF_W1 (OFF_WP + N_WP)        // 3456
#define N_W1   (48 * 64)              // w1:   [c][o_pair]          = 3072
#define OFF_W2 (OFF_W1 + N_W1)        // 6528
#define N_W2   (128 * 64)             // w2:   [c][o_pair]          = 8192
#define OFF_W3 (OFF_W2 + N_W2)        // 14720
#define N_W3   (128 * 8)              // w3:   [h2ch][dx_pair]      = 1024
#define OFF_B1 (OFF_W3 + N_W3)        // 15744  (64 pairs)
#define OFF_B2 (OFF_B1 + 64)          // 15808  (64 pairs)
#define NPACK  (OFF_B2 + 64)          // 15872 ull = 126976 bytes

// SMEM exchange regions (ull units)
#define XCH_P   NPACK                 // p exchange: [24 pairs][256 pix]
#define XCH_P_N (24 * PIXPB)          // 6144
#define XCH_H2  (XCH_P + XCH_P_N)     // h2 partials: 2 bufs x [8][256]
#define XCH_H2N (2 * 8 * PIXPB)       // 4096
#define SMEM_ULL (XCH_H2 + XCH_H2N)   // 26112 ull
#define SMEM_BYTES (SMEM_ULL * 8)     // 208896 B

__device__ __align__(16) float2 g_packed[NPACK];
__device__ float g_buf0[BV * CHN * HWSZ];
__device__ float g_buf1[BV * CHN * HWSZ];

// ---- packed f32x2 helpers --------------------------------------------------
__device__ __forceinline__ ull pk2(float a, float b) {
    ull r;
    asm("mov.b64 %0, {%1, %2};" : "=l"(r)
        : "r"(__float_as_uint(a)), "r"(__float_as_uint(b)));
    return r;
}
__device__ __forceinline__ void upk2(ull v, float& a, float& b) {
    unsigned int lo, hi;
    asm("mov.b64 {%0, %1}, %2;" : "=r"(lo), "=r"(hi) : "l"(v));
    a = __uint_as_float(lo);
    b = __uint_as_float(hi);
}
__device__ __forceinline__ ull f2fma(ull a, ull b, ull c) {
    ull d;
    asm("fma.rn.f32x2 %0, %1, %2, %3;" : "=l"(d) : "l"(a), "l"(b), "l"(c));
    return d;
}
__device__ __forceinline__ ull f2add(ull a, ull b) {
    ull d;
    asm("add.rn.f32x2 %0, %1, %2;" : "=l"(d) : "l"(a), "l"(b));
    return d;
}

// ---- weight packing kernel (tiny, once) ------------------------------------
__global__ void nca_pack(const float* __restrict__ wp, const float* __restrict__ w1,
                         const float* __restrict__ b1, const float* __restrict__ w2,
                         const float* __restrict__ b2, const float* __restrict__ w3) {
    int i = blockIdx.x * blockDim.x + threadIdx.x;
    if (i >= NPACK) return;
    float lo, hi;
    if (i < OFF_W1) {                       // conv weights (OIHW, O=48,I=16,3x3)
        int oc2 = i % 24;
        int r   = i / 24;
        int ic  = r / 9;
        int t   = r % 9;
        lo = wp[((2 * oc2) * 16 + ic) * 9 + t];
        hi = wp[((2 * oc2 + 1) * 16 + ic) * 9 + t];
    } else if (i < OFF_W2) {                // w1 [128,48]
        int j  = i - OFF_W1;
        int o2 = j % 64;
        int c  = j / 64;
        lo = w1[(2 * o2) * 48 + c];
        hi = w1[(2 * o2 + 1) * 48 + c];
    } else if (i < OFF_W3) {                // w2 [128,128]
        int j  = i - OFF_W2;
        int o2 = j % 64;
        int c  = j / 64;
        lo = w2[(2 * o2) * 128 + c];
        hi = w2[(2 * o2 + 1) * 128 + c];
    } else if (i < OFF_B1) {                // w3 [16,128] -> [h2ch][dx_pair]
        int j  = i - OFF_W3;
        int k2 = j % 8;
        int o  = j / 8;
        lo = w3[(2 * k2) * 128 + o];
        hi = w3[(2 * k2 + 1) * 128 + o];
    } else if (i < OFF_B2) {                // b1 [128]
        int j = i - OFF_B1;
        lo = b1[2 * j];
        hi = b1[2 * j + 1];
    } else {                                // b2 [128]
        int j = i - OFF_B2;
        lo = b2[2 * j];
        hi = b2[2 * j + 1];
    }
    g_packed[i] = make_float2(lo, hi);
}

// ---- fused CA step (pair-split) --------------------------------------------
// src_sel: 0=external input, 1=g_buf0, 2=g_buf1
// dst_sel: 1=g_buf0, 2=g_buf1, 3=external output
__global__ __launch_bounds__(NTHR, 1)
void nca_step(const float* __restrict__ src_ext, float* __restrict__ dst_ext,
              int src_sel, int dst_sel) {
    extern __shared__ ull sw[];

    int tid  = threadIdx.x;
    int half = tid >> 8;          // 0: channels-low warps 0-7, 1: high warps 8-15
    int pix  = tid & 255;

    // stage packed weights into SMEM
    {
        const float4* gp = (const float4*)g_packed;
        float4*       sp = (float4*)sw;
        for (int i = tid; i < NPACK / 2; i += NTHR) sp[i] = gp[i];
    }
    __syncthreads();

    const ull* wp2 = sw + OFF_WP;
    const ull* w1p = sw + OFF_W1;
    const ull* w2p = sw + OFF_W2;
    const ull* w3p = sw + OFF_W3;

    const float* src = (src_sel == 0) ? src_ext : ((src_sel == 1) ? g_buf0 : g_buf1);
    float*       dst = (dst_sel == 3) ? dst_ext : ((dst_sel == 1) ? g_buf0 : g_buf1);

    int idx = blockIdx.x * PIXPB + pix;
    int b   = idx / HWSZ;
    int rem = idx - b * HWSZ;
    int y   = rem / WW;
    int x   = rem - y * WW;

    const float* xb = src + b * CHN * HWSZ;

    // ---- 3x3 perception conv: my 24 p channels = 12 f32x2 pairs ----
    {
        ull p2[12];
        #pragma unroll
        for (int i = 0; i < 12; i++) p2[i] = 0ull;

        #pragma unroll 1
        for (int ic = 0; ic < CHN; ic++) {
            const float* xc = xb + ic * HWSZ;
            float v[9];
            #pragma unroll
            for (int t = 0; t < 9; t++) {
                int yy = y + t / 3 - 1;
                int xx = x + t % 3 - 1;
                bool ok = ((unsigned)yy < HH) && ((unsigned)xx < WW);
                v[t] = ok ? __ldg(xc + yy * WW + xx) : 0.0f;
            }
            #pragma unroll
            for (int t = 0; t < 9; t++) {
                ull vv = pk2(v[t], v[t]);
                const ulonglong2* wr =
                    (const ulonglong2*)(wp2 + (ic * 9 + t) * 24 + half * 12);
                #pragma unroll
                for (int j = 0; j < 6; j++) {
                    ulonglong2 w2v = wr[j];
                    p2[2 * j]     = f2fma(w2v.x, vv, p2[2 * j]);
                    p2[2 * j + 1] = f2fma(w2v.y, vv, p2[2 * j + 1]);
                }
            }
        }
        // publish my 12 p pairs: layout [pair(24)][pix(256)]
        #pragma unroll
        for (int j = 0; j < 12; j++)
            sw[XCH_P + (half * 12 + j) * PIXPB + pix] = p2[j];
    }
    __syncthreads();

    // ---- h1 half = relu(W1 p + b1): my 64 ch = 32 pairs ----
    ull h1[32];
    {
        const ulonglong2* bb = (const ulonglong2*)(sw + OFF_B1 + half * 32);
        #pragma unroll
        for (int j = 0; j < 16; j++) {
            ulonglong2 t = bb[j];
            h1[2 * j]     = t.x;
            h1[2 * j + 1] = t.y;
        }
    }
    #pragma unroll 1
    for (int c2 = 0; c2 < 24; c2++) {
        ull pp = sw[XCH_P + c2 * PIXPB + pix];
        float a, bvl;
        upk2(pp, a, bvl);
        ull ua = pk2(a, a), ub = pk2(bvl, bvl);
        const ulonglong2* r0 = (const ulonglong2*)(w1p + (2 * c2) * 64 + half * 32);
        const ulonglong2* r1 = (const ulonglong2*)(w1p + (2 * c2 + 1) * 64 + half * 32);
        #pragma unroll
        for (int j = 0; j < 16; j++) {
            ulonglong2 t = r0[j];
            h1[2 * j]     = f2fma(t.x, ua, h1[2 * j]);
            h1[2 * j + 1] = f2fma(t.y, ua, h1[2 * j + 1]);
        }
        #pragma unroll
        for (int j = 0; j < 16; j++) {
            ulonglong2 t = r1[j];
            h1[2 * j]     = f2fma(t.x, ub, h1[2 * j]);
            h1[2 * j + 1] = f2fma(t.y, ub, h1[2 * j + 1]);
        }
    }
    #pragma unroll
    for (int j = 0; j < 32; j++) {   // relu
        float a, bvl;
        upk2(h1[j], a, bvl);
        h1[j] = pk2(fmaxf(a, 0.0f), fmaxf(bvl, 0.0f));
    }

    // ---- h2 in 8 chunks of 16 ch; partial over my h1-half, pair-sum in SMEM;
    //      chunk owner applies bias+relu and accumulates w3 into dx ----
    ull dx2[8];
    #pragma unroll
    for (int i = 0; i < 8; i++) dx2[i] = 0ull;

    #pragma unroll 1
    for (int q = 0; q < 8; q++) {
        bool owner = ((q >> 2) == half);   // chunks 0-3 -> half0, 4-7 -> half1
        ull acc[8];
        if (owner) {
            const ulonglong2* bb = (const ulonglong2*)(sw + OFF_B2 + q * 8);
            #pragma unroll
            for (int j = 0; j < 4; j++) {
                ulonglong2 t = bb[j];
                acc[2 * j]     = t.x;
                acc[2 * j + 1] = t.y;
            }
        } else {
            #pragma unroll
            for (int j = 0; j < 8; j++) acc[j] = 0ull;
        }

        #pragma unroll 1
        for (int c2l = 0; c2l < 32; c2l++) {
            int cg = half * 64 + 2 * c2l;
            float a, bvl;
            upk2(h1[c2l], a, bvl);
            ull ua = pk2(a, a), ub = pk2(bvl, bvl);
            const ulonglong2* r0 = (const ulonglong2*)(w2p + cg * 64 + q * 8);
            const ulonglong2* r1 = (const ulonglong2*)(w2p + (cg + 1) * 64 + q * 8);
            #pragma unroll
            for (int j = 0; j < 4; j++) {
                ulonglong2 t = r0[j];
                acc[2 * j]     = f2fma(t.x, ua, acc[2 * j]);
                acc[2 * j + 1] = f2fma(t.y, ua, acc[2 * j + 1]);
            }
            #pragma unroll
            for (int j = 0; j < 4; j++) {
                ulonglong2 t = r1[j];
                acc[2 * j]     = f2fma(t.x, ub, acc[2 * j]);
                acc[2 * j + 1] = f2fma(t.y, ub, acc[2 * j + 1]);
            }
        }

        ull* buf = sw + XCH_H2 + (q & 1) * (8 * PIXPB);
        if (!owner) {
            #pragma unroll
            for (int j = 0; j < 8; j++) buf[j * PIXPB + pix] = acc[j];
        }
        __syncthreads();
        if (owner) {
            #pragma unroll
            for (int j = 0; j < 8; j++) acc[j] = f2add(acc[j], buf[j * PIXPB + pix]);
            // relu(h2 chunk) -> dx += W3 h2
            #pragma unroll
            for (int j = 0; j < 8; j++) {
                float u, vv;
                upk2(acc[j], u, vv);
                u  = fmaxf(u, 0.0f);
                vv = fmaxf(vv, 0.0f);
                int o0 = q * 16 + 2 * j;
                ull uu = pk2(u, u), vv2 = pk2(vv, vv);
                const ulonglong2* w30 = (const ulonglong2*)(w3p + o0 * 8);
                const ulonglong2* w31 = (const ulonglong2*)(w3p + (o0 + 1) * 8);
                #pragma unroll
                for (int k = 0; k < 4; k++) {
                    ulonglong2 t = w30[k];
                    dx2[2 * k]     = f2fma(t.x, uu, dx2[2 * k]);
                    dx2[2 * k + 1] = f2fma(t.y, uu, dx2[2 * k + 1]);
                }
                #pragma unroll
                for (int k = 0; k < 4; k++) {
                    ulonglong2 t = w31[k];
                    dx2[2 * k]     = f2fma(t.x, vv2, dx2[2 * k]);
                    dx2[2 * k + 1] = f2fma(t.y, vv2, dx2[2 * k + 1]);
                }
            }
        }
    }

    // ---- pair-sum dx, residual + clamp + store (half0 finalizes) ----
    {
        ull* buf = sw + XCH_H2;   // safe to reuse after the sync below
        __syncthreads();
        if (half == 1) {
            #pragma unroll
            for (int j = 0; j < 8; j++) buf[j * PIXPB + pix] = dx2[j];
        }
        __syncthreads();
        if (half == 0) {
            float* db = dst + b * CHN * HWSZ;
            #pragma unroll
            for (int k2 = 0; k2 < 8; k2++) {
                ull s = f2add(dx2[k2], buf[k2 * PIXPB + pix]);
                float d0, d1;
                upk2(s, d0, d1);
                int c0 = 2 * k2;
                float x0 = __ldg(xb + c0 * HWSZ + rem);
                float x1 = __ldg(xb + (c0 + 1) * HWSZ + rem);
                db[c0 * HWSZ + rem]       = fminf(fmaxf(x0 + d0, 0.0f), 1.0f);
                db[(c0 + 1) * HWSZ + rem] = fminf(fmaxf(x1 + d1, 0.0f), 1.0f);
            }
        }
    }
}

// ---------------------------------------------------------------------------
extern "C" void kernel_launch(void* const* d_in, const int* in_sizes, int n_in,
                              void* d_out, int out_size) {
    const float* x  = (const float*)d_in[0];
    const float* wp = (const float*)d_in[1];
    const float* w1 = (const float*)d_in[2];
    const float* b1 = (const float*)d_in[3];
    const float* w2 = (const float*)d_in[4];
    const float* b2 = (const float*)d_in[5];
    const float* w3 = (const float*)d_in[6];
    float* out = (float*)d_out;

    cudaFuncSetAttribute(nca_step, cudaFuncAttributeMaxDynamicSharedMemorySize,
                         SMEM_BYTES);

    nca_pack<<<(NPACK + 255) / 256, 256>>>(wp, w1, b1, w2, b2, w3);

    for (int s = 0; s < NSTEPS; s++) {
        int ssel = (s == 0) ? 0 : (((s - 1) & 1) ? 2 : 1);
        int dsel = (s == NSTEPS - 1) ? 3 : ((s & 1) ? 2 : 1);
        nca_step<<<NBLK, NTHR, SMEM_BYTES>>>(x, out, ssel, dsel);
    }
}

// round 9
// speedup vs baseline: 1.3635x; 1.3635x over previous
#include <cuda_runtime.h>
#include <cstdint>

// ---------------------------------------------------------------------------
// NeuralCA: 40 steps of  x = clip(x + MLP(conv3x3(x)), 0, 1)
// Eighth-split x 4 pixels/thread: 256 thr/CTA = 128 pixels, 1568 blocks.
// Each warp owns 1/8 of channels; every SMEM weight load is amortized over
// 4 pixels -> L1/SMEM wavefronts drop ~4x vs pair-split; FMA-pipe bound.
// Activations (p, h1) stream via SMEM; dx 8-way reduce reuses h1 region.
// ---------------------------------------------------------------------------

#define BV     4
#define CHN    16
#define HH     224
#define WW     224
#define HWSZ   (HH * WW)
#define NSTEPS 40
#define NPIX   (BV * HWSZ)            // 200704
#define NTHR   256
#define PIXPB  128
#define NBLK   (NPIX / PIXPB)         // 1568

typedef unsigned long long ull;

// packed-weight layout (float2 units == ull slots)
#define OFF_WP 0
#define N_WP   (16 * 9 * 24)          // conv: [ic][tap][oc_pair]   = 3456
#define OFF_W1 (OFF_WP + N_WP)        // 3456
#define N_W1   (48 * 64)              // w1:   [c][o_pair]          = 3072
#define OFF_W2 (OFF_W1 + N_W1)        // 6528
#define N_W2   (128 * 64)             // w2:   [c][o_pair]          = 8192
#define OFF_W3 (OFF_W2 + N_W2)        // 14720
#define N_W3   (128 * 8)              // w3:   [h2ch][dx_pair]      = 1024
#define OFF_B1 (OFF_W3 + N_W3)        // 15744  (64 pairs)
#define OFF_B2 (OFF_B1 + 64)          // 15808  (64 pairs)
#define NPACK  (OFF_B2 + 64)          // 15872 ull = 126976 bytes

// SMEM activation regions (ull units)
#define XCH_P   NPACK                 // p:  [24 pair-rows][128 pix] = 3072
#define XCH_P_N (24 * PIXPB)
#define XCH_H1  (XCH_P + XCH_P_N)     // h1: [64 pair-rows][128 pix] = 8192
#define XCH_H1N (64 * PIXPB)          // (reused for dx partials [8e][8][128])
#define SMEM_ULL (XCH_H1 + XCH_H1N)   // 27136 ull
#define SMEM_BYTES (SMEM_ULL * 8)     // 217088 B

__device__ __align__(16) float2 g_packed[NPACK];
__device__ float g_buf0[BV * CHN * HWSZ];
__device__ float g_buf1[BV * CHN * HWSZ];

// ---- packed f32x2 helpers --------------------------------------------------
__device__ __forceinline__ ull pk2(float a, float b) {
    ull r;
    asm("mov.b64 %0, {%1, %2};" : "=l"(r)
        : "r"(__float_as_uint(a)), "r"(__float_as_uint(b)));
    return r;
}
__device__ __forceinline__ void upk2(ull v, float& a, float& b) {
    unsigned int lo, hi;
    asm("mov.b64 {%0, %1}, %2;" : "=r"(lo), "=r"(hi) : "l"(v));
    a = __uint_as_float(lo);
    b = __uint_as_float(hi);
}
__device__ __forceinline__ ull f2fma(ull a, ull b, ull c) {
    ull d;
    asm("fma.rn.f32x2 %0, %1, %2, %3;" : "=l"(d) : "l"(a), "l"(b), "l"(c));
    return d;
}
__device__ __forceinline__ ull f2add(ull a, ull b) {
    ull d;
    asm("add.rn.f32x2 %0, %1, %2;" : "=l"(d) : "l"(a), "l"(b));
    return d;
}
__device__ __forceinline__ ull f2relu(ull a) {
    float x, y;
    upk2(a, x, y);
    return pk2(fmaxf(x, 0.0f), fmaxf(y, 0.0f));
}

// ---- weight packing kernel (tiny, once) ------------------------------------
__global__ void nca_pack(const float* __restrict__ wp, const float* __restrict__ w1,
                         const float* __restrict__ b1, const float* __restrict__ w2,
                         const float* __restrict__ b2, const float* __restrict__ w3) {
    int i = blockIdx.x * blockDim.x + threadIdx.x;
    if (i >= NPACK) return;
    float lo, hi;
    if (i < OFF_W1) {                       // conv weights (OIHW, O=48,I=16,3x3)
        int oc2 = i % 24;
        int r   = i / 24;
        int ic  = r / 9;
        int t   = r % 9;
        lo = wp[((2 * oc2) * 16 + ic) * 9 + t];
        hi = wp[((2 * oc2 + 1) * 16 + ic) * 9 + t];
    } else if (i < OFF_W2) {                // w1 [128,48]
        int j  = i - OFF_W1;
        int o2 = j % 64;
        int c  = j / 64;
        lo = w1[(2 * o2) * 48 + c];
        hi = w1[(2 * o2 + 1) * 48 + c];
    } else if (i < OFF_W3) {                // w2 [128,128]
        int j  = i - OFF_W2;
        int o2 = j % 64;
        int c  = j / 64;
        lo = w2[(2 * o2) * 128 + c];
        hi = w2[(2 * o2 + 1) * 128 + c];
    } else if (i < OFF_B1) {                // w3 [16,128] -> [h2ch][dx_pair]
        int j  = i - OFF_W3;
        int k2 = j % 8;
        int o  = j / 8;
        lo = w3[(2 * k2) * 128 + o];
        hi = w3[(2 * k2 + 1) * 128 + o];
    } else if (i < OFF_B2) {                // b1 [128]
        int j = i - OFF_B1;
        lo = b1[2 * j];
        hi = b1[2 * j + 1];
    } else {                                // b2 [128]
        int j = i - OFF_B2;
        lo = b2[2 * j];
        hi = b2[2 * j + 1];
    }
    g_packed[i] = make_float2(lo, hi);
}

// ---- fused CA step (eighth-split x 4 pixels/thread) ------------------------
// src_sel: 0=external input, 1=g_buf0, 2=g_buf1
// dst_sel: 1=g_buf0, 2=g_buf1, 3=external output
__global__ __launch_bounds__(NTHR, 1)
void nca_step(const float* __restrict__ src_ext, float* __restrict__ dst_ext,
              int src_sel, int dst_sel) {
    extern __shared__ ull sw[];

    int tid = threadIdx.x;
    int e   = tid >> 5;           // eighth (warp id): owns 1/8 of channels
    int s   = tid & 31;           // pixel slot

    // stage packed weights into SMEM
    {
        const float4* gp = (const float4*)g_packed;
        float4*       sp = (float4*)sw;
        for (int i = tid; i < NPACK / 2; i += NTHR) sp[i] = gp[i];
    }
    __syncthreads();

    const ull* wp2 = sw + OFF_WP;
    const ull* w1p = sw + OFF_W1;
    const ull* w2p = sw + OFF_W2;
    const ull* w3p = sw + OFF_W3;

    const float* src = (src_sel == 0) ? src_ext : ((src_sel == 1) ? g_buf0 : g_buf1);
    float*       dst = (dst_sel == 3) ? dst_ext : ((dst_sel == 1) ? g_buf0 : g_buf1);

    // 4 pixels/thread: CTA pixels [blockIdx*128, +128); mine: s+32k
    int py[4], px[4];
    const float* pxb[4];
    #pragma unroll
    for (int k = 0; k < 4; k++) {
        int idx = blockIdx.x * PIXPB + s + 32 * k;
        int b   = idx / HWSZ;
        int rm  = idx - b * HWSZ;
        py[k]   = rm / WW;
        px[k]   = rm - py[k] * WW;
        pxb[k]  = src + b * CHN * HWSZ;
    }

    // ---- 3x3 perception conv: my 6 p-ch = 3 pairs x 4 pix ----
    {
        ull p2[12];
        #pragma unroll
        for (int i = 0; i < 12; i++) p2[i] = 0ull;

        #pragma unroll 1
        for (int ic = 0; ic < CHN; ic++) {
            #pragma unroll
            for (int t = 0; t < 9; t++) {
                int dy = t / 3 - 1, dxo = t % 3 - 1;
                float v[4];
                #pragma unroll
                for (int k = 0; k < 4; k++) {
                    int yy = py[k] + dy, xx = px[k] + dxo;
                    bool ok = ((unsigned)yy < HH) && ((unsigned)xx < WW);
                    v[k] = ok ? __ldg(pxb[k] + ic * HWSZ + yy * WW + xx) : 0.0f;
                }
                ull w0 = wp2[(ic * 9 + t) * 24 + 3 * e + 0];
                ull w1v = wp2[(ic * 9 + t) * 24 + 3 * e + 1];
                ull w2v = wp2[(ic * 9 + t) * 24 + 3 * e + 2];
                #pragma unroll
                for (int k = 0; k < 4; k++) {
                    ull vv = pk2(v[k], v[k]);
                    p2[0 + k]  = f2fma(w0,  vv, p2[0 + k]);
                    p2[4 + k]  = f2fma(w1v, vv, p2[4 + k]);
                    p2[8 + k]  = f2fma(w2v, vv, p2[8 + k]);
                }
            }
        }
        #pragma unroll
        for (int j = 0; j < 3; j++)
            #pragma unroll
            for (int k = 0; k < 4; k++)
                sw[XCH_P + (3 * e + j) * PIXPB + s + 32 * k] = p2[j * 4 + k];
    }
    __syncthreads();

    // ---- h1 = relu(W1 p + b1): my 8 pairs x 4 pix -> SMEM ----
    {
        ull h1[32];
        #pragma unroll
        for (int j = 0; j < 8; j++) {
            ull bj = sw[OFF_B1 + 8 * e + j];
            #pragma unroll
            for (int k = 0; k < 4; k++) h1[j * 4 + k] = bj;
        }
        #pragma unroll 1
        for (int c2 = 0; c2 < 24; c2++) {
            float fa[4], fb[4];
            #pragma unroll
            for (int k = 0; k < 4; k++) {
                ull pp = sw[XCH_P + c2 * PIXPB + s + 32 * k];
                upk2(pp, fa[k], fb[k]);
            }
            {
                const ulonglong2* W = (const ulonglong2*)(w1p + (2 * c2) * 64 + 8 * e);
                ull wa[8];
                #pragma unroll
                for (int m = 0; m < 4; m++) { ulonglong2 t2 = W[m]; wa[2*m] = t2.x; wa[2*m+1] = t2.y; }
                #pragma unroll
                for (int k = 0; k < 4; k++) {
                    ull ua = pk2(fa[k], fa[k]);
                    #pragma unroll
                    for (int j = 0; j < 8; j++) h1[j * 4 + k] = f2fma(wa[j], ua, h1[j * 4 + k]);
                }
            }
            {
                const ulonglong2* W = (const ulonglong2*)(w1p + (2 * c2 + 1) * 64 + 8 * e);
                ull wb[8];
                #pragma unroll
                for (int m = 0; m < 4; m++) { ulonglong2 t2 = W[m]; wb[2*m] = t2.x; wb[2*m+1] = t2.y; }
                #pragma unroll
                for (int k = 0; k < 4; k++) {
                    ull ub = pk2(fb[k], fb[k]);
                    #pragma unroll
                    for (int j = 0; j < 8; j++) h1[j * 4 + k] = f2fma(wb[j], ub, h1[j * 4 + k]);
                }
            }
        }
        #pragma unroll
        for (int j = 0; j < 8; j++)
            #pragma unroll
            for (int k = 0; k < 4; k++)
                sw[XCH_H1 + (8 * e + j) * PIXPB + s + 32 * k] = f2relu(h1[j * 4 + k]);
    }
    __syncthreads();

    // ---- h2 = relu(W2 h1 + b2), my 16 ch in 2 rounds of 4 pairs; dx += W3 h2
    ull dx2[32];
    #pragma unroll
    for (int i = 0; i < 32; i++) dx2[i] = 0ull;

    #pragma unroll 1
    for (int r = 0; r < 2; r++) {
        ull acc[16];
        #pragma unroll
        for (int j = 0; j < 4; j++) {
            ull bj = sw[OFF_B2 + 8 * e + 4 * r + j];
            #pragma unroll
            for (int k = 0; k < 4; k++) acc[j * 4 + k] = bj;
        }
        #pragma unroll 1
        for (int c2 = 0; c2 < 64; c2++) {
            float fa[4], fb[4];
            #pragma unroll
            for (int k = 0; k < 4; k++) {
                ull hh = sw[XCH_H1 + c2 * PIXPB + s + 32 * k];
                upk2(hh, fa[k], fb[k]);
            }
            {
                const ulonglong2* W = (const ulonglong2*)(w2p + (2 * c2) * 64 + 8 * e + 4 * r);
                ulonglong2 t0 = W[0], t1 = W[1];
                #pragma unroll
                for (int k = 0; k < 4; k++) {
                    ull ua = pk2(fa[k], fa[k]);
                    acc[0  + k] = f2fma(t0.x, ua, acc[0  + k]);
                    acc[4  + k] = f2fma(t0.y, ua, acc[4  + k]);
                    acc[8  + k] = f2fma(t1.x, ua, acc[8  + k]);
                    acc[12 + k] = f2fma(t1.y, ua, acc[12 + k]);
                }
            }
            {
                const ulonglong2* W = (const ulonglong2*)(w2p + (2 * c2 + 1) * 64 + 8 * e + 4 * r);
                ulonglong2 t0 = W[0], t1 = W[1];
                #pragma unroll
                for (int k = 0; k < 4; k++) {
                    ull ub = pk2(fb[k], fb[k]);
                    acc[0  + k] = f2fma(t0.x, ub, acc[0  + k]);
                    acc[4  + k] = f2fma(t0.y, ub, acc[4  + k]);
                    acc[8  + k] = f2fma(t1.x, ub, acc[8  + k]);
                    acc[12 + k] = f2fma(t1.y, ub, acc[12 + k]);
                }
            }
        }
        // relu(h2 chunk) -> dx += W3 h2
        #pragma unroll
        for (int j = 0; j < 4; j++) {
            int g0 = 2 * (8 * e + 4 * r + j);
            const ulonglong2* W30 = (const ulonglong2*)(w3p + g0 * 8);
            const ulonglong2* W31 = (const ulonglong2*)(w3p + (g0 + 1) * 8);
            ull w30[8], w31[8];
            #pragma unroll
            for (int m = 0; m < 4; m++) { ulonglong2 t2 = W30[m]; w30[2*m] = t2.x; w30[2*m+1] = t2.y; }
            #pragma unroll
            for (int m = 0; m < 4; m++) { ulonglong2 t2 = W31[m]; w31[2*m] = t2.x; w31[2*m+1] = t2.y; }
            #pragma unroll
            for (int k = 0; k < 4; k++) {
                float u, vv;
                upk2(acc[j * 4 + k], u, vv);
                u  = fmaxf(u, 0.0f);
                vv = fmaxf(vv, 0.0f);
                ull uu = pk2(u, u), vv2 = pk2(vv, vv);
                #pragma unroll
                for (int m = 0; m < 8; m++) dx2[m * 4 + k] = f2fma(w30[m], uu, dx2[m * 4 + k]);
                #pragma unroll
                for (int m = 0; m < 8; m++) dx2[m * 4 + k] = f2fma(w31[m], vv2, dx2[m * 4 + k]);
            }
        }
    }

    // ---- 8-way dx reduce via SMEM (reuse h1 region), residual+clamp+store --
    __syncthreads();   // all h1 reads done; safe to overwrite region
    #pragma unroll
    for (int m = 0; m < 8; m++)
        #pragma unroll
        for (int k = 0; k < 4; k++)
            sw[XCH_H1 + (e * 8 + m) * PIXPB + s + 32 * k] = dx2[m * 4 + k];
    __syncthreads();

    #pragma unroll
    for (int c = 0; c < 4; c++) {
        int cell = tid + NTHR * c;        // 0..1023 = [dx pair j(8)] x [pix(128)]
        int j    = cell >> 7;
        int pxl  = cell & 127;
        ull sum  = sw[XCH_H1 + j * PIXPB + pxl];
        #pragma unroll
        for (int eo = 1; eo < 8; eo++)
            sum = f2add(sum, sw[XCH_H1 + (eo * 8 + j) * PIXPB + pxl]);
        float d0, d1;
        upk2(sum, d0, d1);
        int gidx = blockIdx.x * PIXPB + pxl;
        int b2   = gidx / HWSZ;
        int rr   = gidx - b2 * HWSZ;
        const float* xbb = src + b2 * CHN * HWSZ;
        float*       dbb = dst + b2 * CHN * HWSZ;
        int c0 = 2 * j;
        float x0 = __ldg(xbb + c0 * HWSZ + rr);
        float x1 = __ldg(xbb + (c0 + 1) * HWSZ + rr);
        dbb[c0 * HWSZ + rr]       = fminf(fmaxf(x0 + d0, 0.0f), 1.0f);
        dbb[(c0 + 1) * HWSZ + rr] = fminf(fmaxf(x1 + d1, 0.0f), 1.0f);
    }
}

// ---------------------------------------------------------------------------
extern "C" void kernel_launch(void* const* d_in, const int* in_sizes, int n_in,
                              void* d_out, int out_size) {
    const float* x  = (const float*)d_in[0];
    const float* wp = (const float*)d_in[1];
    const float* w1 = (const float*)d_in[2];
    const float* b1 = (const float*)d_in[3];
    const float* w2 = (const float*)d_in[4];
    const float* b2 = (const float*)d_in[5];
    const float* w3 = (const float*)d_in[6];
    float* out = (float*)d_out;

    cudaFuncSetAttribute(nca_step, cudaFuncAttributeMaxDynamicSharedMemorySize,
                         SMEM_BYTES);

    nca_pack<<<(NPACK + 255) / 256, 256>>>(wp, w1, b1, w2, b2, w3);

    for (int s = 0; s < NSTEPS; s++) {
        int ssel = (s == 0) ? 0 : (((s - 1) & 1) ? 2 : 1);
        int dsel = (s == NSTEPS - 1) ? 3 : ((s & 1) ? 2 : 1);
        nca_step<<<NBLK, NTHR, SMEM_BYTES>>>(x, out, ssel, dsel);
    }
}

// round 10
// speedup vs baseline: 1.4003x; 1.0270x over previous
#include <cuda_runtime.h>
#include <cstdint>

// ---------------------------------------------------------------------------
// NeuralCA: 40 steps of  x = clip(x + MLP(conv3x3(x)), 0, 1)
// Eighth-split x 4 pixels/thread; w2 computed in ONE round (8 output-pairs
// per thread) so each activation is loaded/unpacked/duplicated once per
// input channel -> w2 non-FMA overhead ~halves vs 2-round version.
// 256 thr/CTA = 128 pixels, 1568 blocks, weights packed f32x2 in SMEM.
// ---------------------------------------------------------------------------

#define BV     4
#define CHN    16
#define HH     224
#define WW     224
#define HWSZ   (HH * WW)
#define NSTEPS 40
#define NPIX   (BV * HWSZ)            // 200704
#define NTHR   256
#define PIXPB  128
#define NBLK   (NPIX / PIXPB)         // 1568

typedef unsigned long long ull;

// packed-weight layout (float2 units == ull slots)
#define OFF_WP 0
#define N_WP   (16 * 9 * 24)          // conv: [ic][tap][oc_pair]   = 3456
#define OFF_W1 (OFF_WP + N_WP)        // 3456
#define N_W1   (48 * 64)              // w1:   [c][o_pair]          = 3072
#define OFF_W2 (OFF_W1 + N_W1)        // 6528
#define N_W2   (128 * 64)             // w2:   [c][o_pair]          = 8192
#define OFF_W3 (OFF_W2 + N_W2)        // 14720
#define N_W3   (128 * 8)              // w3:   [h2ch][dx_pair]      = 1024
#define OFF_B1 (OFF_W3 + N_W3)        // 15744  (64 pairs)
#define OFF_B2 (OFF_B1 + 64)          // 15808  (64 pairs)
#define NPACK  (OFF_B2 + 64)          // 15872 ull = 126976 bytes

// SMEM activation regions (ull units)
#define XCH_P   NPACK                 // p:  [24 pair-rows][128 pix] = 3072
#define XCH_P_N (24 * PIXPB)
#define XCH_H1  (XCH_P + XCH_P_N)     // h1: [64 pair-rows][128 pix] = 8192
#define XCH_H1N (64 * PIXPB)          // (reused for dx partials [8e][8][128])
#define SMEM_ULL (XCH_H1 + XCH_H1N)   // 27136 ull
#define SMEM_BYTES (SMEM_ULL * 8)     // 217088 B

__device__ __align__(16) float2 g_packed[NPACK];
__device__ float g_buf0[BV * CHN * HWSZ];
__device__ float g_buf1[BV * CHN * HWSZ];

// ---- packed f32x2 helpers --------------------------------------------------
__device__ __forceinline__ ull pk2(float a, float b) {
    ull r;
    asm("mov.b64 %0, {%1, %2};" : "=l"(r)
        : "r"(__float_as_uint(a)), "r"(__float_as_uint(b)));
    return r;
}
__device__ __forceinline__ void upk2(ull v, float& a, float& b) {
    unsigned int lo, hi;
    asm("mov.b64 {%0, %1}, %2;" : "=r"(lo), "=r"(hi) : "l"(v));
    a = __uint_as_float(lo);
    b = __uint_as_float(hi);
}
__device__ __forceinline__ ull f2fma(ull a, ull b, ull c) {
    ull d;
    asm("fma.rn.f32x2 %0, %1, %2, %3;" : "=l"(d) : "l"(a), "l"(b), "l"(c));
    return d;
}
__device__ __forceinline__ ull f2add(ull a, ull b) {
    ull d;
    asm("add.rn.f32x2 %0, %1, %2;" : "=l"(d) : "l"(a), "l"(b));
    return d;
}
__device__ __forceinline__ ull f2relu(ull a) {
    float x, y;
    upk2(a, x, y);
    return pk2(fmaxf(x, 0.0f), fmaxf(y, 0.0f));
}

// ---- weight packing kernel (tiny, once) ------------------------------------
__global__ void nca_pack(const float* __restrict__ wp, const float* __restrict__ w1,
                         const float* __restrict__ b1, const float* __restrict__ w2,
                         const float* __restrict__ b2, const float* __restrict__ w3) {
    int i = blockIdx.x * blockDim.x + threadIdx.x;
    if (i >= NPACK) return;
    float lo, hi;
    if (i < OFF_W1) {                       // conv weights (OIHW, O=48,I=16,3x3)
        int oc2 = i % 24;
        int r   = i / 24;
        int ic  = r / 9;
        int t   = r % 9;
        lo = wp[((2 * oc2) * 16 + ic) * 9 + t];
        hi = wp[((2 * oc2 + 1) * 16 + ic) * 9 + t];
    } else if (i < OFF_W2) {                // w1 [128,48]
        int j  = i - OFF_W1;
        int o2 = j % 64;
        int c  = j / 64;
        lo = w1[(2 * o2) * 48 + c];
        hi = w1[(2 * o2 + 1) * 48 + c];
    } else if (i < OFF_W3) {                // w2 [128,128]
        int j  = i - OFF_W2;
        int o2 = j % 64;
        int c  = j / 64;
        lo = w2[(2 * o2) * 128 + c];
        hi = w2[(2 * o2 + 1) * 128 + c];
    } else if (i < OFF_B1) {                // w3 [16,128] -> [h2ch][dx_pair]
        int j  = i - OFF_W3;
        int k2 = j % 8;
        int o  = j / 8;
        lo = w3[(2 * k2) * 128 + o];
        hi = w3[(2 * k2 + 1) * 128 + o];
    } else if (i < OFF_B2) {                // b1 [128]
        int j = i - OFF_B1;
        lo = b1[2 * j];
        hi = b1[2 * j + 1];
    } else {                                // b2 [128]
        int j = i - OFF_B2;
        lo = b2[2 * j];
        hi = b2[2 * j + 1];
    }
    g_packed[i] = make_float2(lo, hi);
}

// ---- fused CA step (eighth-split x 4 pixels/thread, 1-round w2) ------------
// src_sel: 0=external input, 1=g_buf0, 2=g_buf1
// dst_sel: 1=g_buf0, 2=g_buf1, 3=external output
__global__ __launch_bounds__(NTHR, 1)
void nca_step(const float* __restrict__ src_ext, float* __restrict__ dst_ext,
              int src_sel, int dst_sel) {
    extern __shared__ ull sw[];

    int tid = threadIdx.x;
    int e   = tid >> 5;           // eighth (warp id): owns 1/8 of channels
    int s   = tid & 31;           // pixel slot

    // stage packed weights into SMEM
    {
        const float4* gp = (const float4*)g_packed;
        float4*       sp = (float4*)sw;
        for (int i = tid; i < NPACK / 2; i += NTHR) sp[i] = gp[i];
    }
    __syncthreads();

    const ull* wp2 = sw + OFF_WP;
    const ull* w1p = sw + OFF_W1;
    const ull* w2p = sw + OFF_W2;
    const ull* w3p = sw + OFF_W3;

    const float* src = (src_sel == 0) ? src_ext : ((src_sel == 1) ? g_buf0 : g_buf1);
    float*       dst = (dst_sel == 3) ? dst_ext : ((dst_sel == 1) ? g_buf0 : g_buf1);

    // 4 pixels/thread: CTA pixels [blockIdx*128, +128); mine: s+32k
    int py[4], px[4];
    const float* pxb[4];
    #pragma unroll
    for (int k = 0; k < 4; k++) {
        int idx = blockIdx.x * PIXPB + s + 32 * k;
        int b   = idx / HWSZ;
        int rm  = idx - b * HWSZ;
        py[k]   = rm / WW;
        px[k]   = rm - py[k] * WW;
        pxb[k]  = src + b * CHN * HWSZ;
    }

    // ---- 3x3 perception conv: my 6 p-ch = 3 pairs x 4 pix ----
    {
        ull p2[12];
        #pragma unroll
        for (int i = 0; i < 12; i++) p2[i] = 0ull;

        #pragma unroll 1
        for (int ic = 0; ic < CHN; ic++) {
            #pragma unroll
            for (int t = 0; t < 9; t++) {
                int dy = t / 3 - 1, dxo = t % 3 - 1;
                float v[4];
                #pragma unroll
                for (int k = 0; k < 4; k++) {
                    int yy = py[k] + dy, xx = px[k] + dxo;
                    bool ok = ((unsigned)yy < HH) && ((unsigned)xx < WW);
                    v[k] = ok ? __ldg(pxb[k] + ic * HWSZ + yy * WW + xx) : 0.0f;
                }
                ull w0 = wp2[(ic * 9 + t) * 24 + 3 * e + 0];
                ull w1v = wp2[(ic * 9 + t) * 24 + 3 * e + 1];
                ull w2v = wp2[(ic * 9 + t) * 24 + 3 * e + 2];
                #pragma unroll
                for (int k = 0; k < 4; k++) {
                    ull vv = pk2(v[k], v[k]);
                    p2[0 + k]  = f2fma(w0,  vv, p2[0 + k]);
                    p2[4 + k]  = f2fma(w1v, vv, p2[4 + k]);
                    p2[8 + k]  = f2fma(w2v, vv, p2[8 + k]);
                }
            }
        }
        #pragma unroll
        for (int j = 0; j < 3; j++)
            #pragma unroll
            for (int k = 0; k < 4; k++)
                sw[XCH_P + (3 * e + j) * PIXPB + s + 32 * k] = p2[j * 4 + k];
    }
    __syncthreads();

    // ---- h1 = relu(W1 p + b1): my 8 pairs x 4 pix -> SMEM ----
    {
        ull h1[32];
        #pragma unroll
        for (int j = 0; j < 8; j++) {
            ull bj = sw[OFF_B1 + 8 * e + j];
            #pragma unroll
            for (int k = 0; k < 4; k++) h1[j * 4 + k] = bj;
        }
        #pragma unroll 1
        for (int c2 = 0; c2 < 24; c2++) {
            float fa[4], fb[4];
            #pragma unroll
            for (int k = 0; k < 4; k++) {
                ull pp = sw[XCH_P + c2 * PIXPB + s + 32 * k];
                upk2(pp, fa[k], fb[k]);
            }
            {
                const ulonglong2* W = (const ulonglong2*)(w1p + (2 * c2) * 64 + 8 * e);
                ull wa[8];
                #pragma unroll
                for (int m = 0; m < 4; m++) { ulonglong2 t2 = W[m]; wa[2*m] = t2.x; wa[2*m+1] = t2.y; }
                #pragma unroll
                for (int k = 0; k < 4; k++) {
                    ull ua = pk2(fa[k], fa[k]);
                    #pragma unroll
                    for (int j = 0; j < 8; j++) h1[j * 4 + k] = f2fma(wa[j], ua, h1[j * 4 + k]);
                }
            }
            {
                const ulonglong2* W = (const ulonglong2*)(w1p + (2 * c2 + 1) * 64 + 8 * e);
                ull wb[8];
                #pragma unroll
                for (int m = 0; m < 4; m++) { ulonglong2 t2 = W[m]; wb[2*m] = t2.x; wb[2*m+1] = t2.y; }
                #pragma unroll
                for (int k = 0; k < 4; k++) {
                    ull ub = pk2(fb[k], fb[k]);
                    #pragma unroll
                    for (int j = 0; j < 8; j++) h1[j * 4 + k] = f2fma(wb[j], ub, h1[j * 4 + k]);
                }
            }
        }
        #pragma unroll
        for (int j = 0; j < 8; j++)
            #pragma unroll
            for (int k = 0; k < 4; k++)
                sw[XCH_H1 + (8 * e + j) * PIXPB + s + 32 * k] = f2relu(h1[j * 4 + k]);
    }
    __syncthreads();

    // ---- h2 = relu(W2 h1 + b2): my 8 pairs x 4 pix in ONE round ----
    ull acc[32];
    #pragma unroll
    for (int j = 0; j < 8; j++) {
        ull bj = sw[OFF_B2 + 8 * e + j];
        #pragma unroll
        for (int k = 0; k < 4; k++) acc[j * 4 + k] = bj;
    }
    #pragma unroll 1
    for (int c2 = 0; c2 < 64; c2++) {
        float fa[4], fb[4];
        #pragma unroll
        for (int k = 0; k < 4; k++) {
            ull hh = sw[XCH_H1 + c2 * PIXPB + s + 32 * k];
            upk2(hh, fa[k], fb[k]);
        }
        {
            const ulonglong2* W = (const ulonglong2*)(w2p + (2 * c2) * 64 + 8 * e);
            ull wa[8];
            #pragma unroll
            for (int m = 0; m < 4; m++) { ulonglong2 t2 = W[m]; wa[2*m] = t2.x; wa[2*m+1] = t2.y; }
            #pragma unroll
            for (int k = 0; k < 4; k++) {
                ull ua = pk2(fa[k], fa[k]);
                #pragma unroll
                for (int j = 0; j < 8; j++) acc[j * 4 + k] = f2fma(wa[j], ua, acc[j * 4 + k]);
            }
        }
        {
            const ulonglong2* W = (const ulonglong2*)(w2p + (2 * c2 + 1) * 64 + 8 * e);
            ull wb[8];
            #pragma unroll
            for (int m = 0; m < 4; m++) { ulonglong2 t2 = W[m]; wb[2*m] = t2.x; wb[2*m+1] = t2.y; }
            #pragma unroll
            for (int k = 0; k < 4; k++) {
                ull ub = pk2(fb[k], fb[k]);
                #pragma unroll
                for (int j = 0; j < 8; j++) acc[j * 4 + k] = f2fma(wb[j], ub, acc[j * 4 + k]);
            }
        }
    }

    // ---- relu(h2) -> dx += W3 h2 (my 16 h2-ch), then 8-way reduce ----
    ull dx2[32];
    #pragma unroll
    for (int i = 0; i < 32; i++) dx2[i] = 0ull;

    #pragma unroll
    for (int j = 0; j < 8; j++) {
        int g0 = 2 * (8 * e + j);
        const ulonglong2* W30 = (const ulonglong2*)(w3p + g0 * 8);
        const ulonglong2* W31 = (const ulonglong2*)(w3p + (g0 + 1) * 8);
        ull w30[8], w31[8];
        #pragma unroll
        for (int m = 0; m < 4; m++) { ulonglong2 t2 = W30[m]; w30[2*m] = t2.x; w30[2*m+1] = t2.y; }
        #pragma unroll
        for (int m = 0; m < 4; m++) { ulonglong2 t2 = W31[m]; w31[2*m] = t2.x; w31[2*m+1] = t2.y; }
        #pragma unroll
        for (int k = 0; k < 4; k++) {
            float u, vv;
            upk2(acc[j * 4 + k], u, vv);
            u  = fmaxf(u, 0.0f);
            vv = fmaxf(vv, 0.0f);
            ull uu = pk2(u, u), vv2 = pk2(vv, vv);
            #pragma unroll
            for (int m = 0; m < 8; m++) dx2[m * 4 + k] = f2fma(w30[m], uu, dx2[m * 4 + k]);
            #pragma unroll
            for (int m = 0; m < 8; m++) dx2[m * 4 + k] = f2fma(w31[m], vv2, dx2[m * 4 + k]);
        }
    }

    // ---- 8-way dx reduce via SMEM (reuse h1 region), residual+clamp+store --
    __syncthreads();   // all h1 reads done; safe to overwrite region
    #pragma unroll
    for (int m = 0; m < 8; m++)
        #pragma unroll
        for (int k = 0; k < 4; k++)
            sw[XCH_H1 + (e * 8 + m) * PIXPB + s + 32 * k] = dx2[m * 4 + k];
    __syncthreads();

    #pragma unroll
    for (int c = 0; c < 4; c++) {
        int cell = tid + NTHR * c;        // 0..1023 = [dx pair j(8)] x [pix(128)]
        int j    = cell >> 7;
        int pxl  = cell & 127;
        ull sum  = sw[XCH_H1 + j * PIXPB + pxl];
        #pragma unroll
        for (int eo = 1; eo < 8; eo++)
            sum = f2add(sum, sw[XCH_H1 + (eo * 8 + j) * PIXPB + pxl]);
        float d0, d1;
        upk2(sum, d0, d1);
        int gidx = blockIdx.x * PIXPB + pxl;
        int b2   = gidx / HWSZ;
        int rr   = gidx - b2 * HWSZ;
        const float* xbb = src + b2 * CHN * HWSZ;
        float*       dbb = dst + b2 * CHN * HWSZ;
        int c0 = 2 * j;
        float x0 = __ldg(xbb + c0 * HWSZ + rr);
        float x1 = __ldg(xbb + (c0 + 1) * HWSZ + rr);
        dbb[c0 * HWSZ + rr]       = fminf(fmaxf(x0 + d0, 0.0f), 1.0f);
        dbb[(c0 + 1) * HWSZ + rr] = fminf(fmaxf(x1 + d1, 0.0f), 1.0f);
    }
}

// ---------------------------------------------------------------------------
extern "C" void kernel_launch(void* const* d_in, const int* in_sizes, int n_in,
                              void* d_out, int out_size) {
    const float* x  = (const float*)d_in[0];
    const float* wp = (const float*)d_in[1];
    const float* w1 = (const float*)d_in[2];
    const float* b1 = (const float*)d_in[3];
    const float* w2 = (const float*)d_in[4];
    const float* b2 = (const float*)d_in[5];
    const float* w3 = (const float*)d_in[6];
    float* out = (float*)d_out;

    cudaFuncSetAttribute(nca_step, cudaFuncAttributeMaxDynamicSharedMemorySize,
                         SMEM_BYTES);

    nca_pack<<<(NPACK + 255) / 256, 256>>>(wp, w1, b1, w2, b2, w3);

    for (int s = 0; s < NSTEPS; s++) {
        int ssel = (s == 0) ? 0 : (((s - 1) & 1) ? 2 : 1);
        int dsel = (s == NSTEPS - 1) ? 3 : ((s & 1) ? 2 : 1);
        nca_step<<<NBLK, NTHR, SMEM_BYTES>>>(x, out, ssel, dsel);
    }
}

// round 11
// speedup vs baseline: 1.5491x; 1.1062x over previous
#include <cuda_runtime.h>
#include <cstdint>

// ---------------------------------------------------------------------------
// NeuralCA: 40 steps of  x = clip(x + MLP(conv3x3(x)), 0, 1)
// Eighth-split x 4 pixels/thread; 1-round w2 (8 output-pairs/thread).
// R11: unroll k-loops x2 so ptxas software-pipelines SMEM/global loads under
// FFMA2s (R10 showed issue pinned at 41.7% by exposed LDS latency).
// 256 thr/CTA = 128 pixels, 1568 blocks, weights packed f32x2 in SMEM.
// ---------------------------------------------------------------------------

#define BV     4
#define CHN    16
#define HH     224
#define WW     224
#define HWSZ   (HH * WW)
#define NSTEPS 40
#define NPIX   (BV * HWSZ)            // 200704
#define NTHR   256
#define PIXPB  128
#define NBLK   (NPIX / PIXPB)         // 1568

typedef unsigned long long ull;

// packed-weight layout (float2 units == ull slots)
#define OFF_WP 0
#define N_WP   (16 * 9 * 24)          // conv: [ic][tap][oc_pair]   = 3456
#define OFF_W1 (OFF_WP + N_WP)        // 3456
#define N_W1   (48 * 64)              // w1:   [c][o_pair]          = 3072
#define OFF_W2 (OFF_W1 + N_W1)        // 6528
#define N_W2   (128 * 64)             // w2:   [c][o_pair]          = 8192
#define OFF_W3 (OFF_W2 + N_W2)        // 14720
#define N_W3   (128 * 8)              // w3:   [h2ch][dx_pair]      = 1024
#define OFF_B1 (OFF_W3 + N_W3)        // 15744  (64 pairs)
#define OFF_B2 (OFF_B1 + 64)          // 15808  (64 pairs)
#define NPACK  (OFF_B2 + 64)          // 15872 ull = 126976 bytes

// SMEM activation regions (ull units)
#define XCH_P   NPACK                 // p:  [24 pair-rows][128 pix] = 3072
#define XCH_P_N (24 * PIXPB)
#define XCH_H1  (XCH_P + XCH_P_N)     // h1: [64 pair-rows][128 pix] = 8192
#define XCH_H1N (64 * PIXPB)          // (reused for dx partials [8e][8][128])
#define SMEM_ULL (XCH_H1 + XCH_H1N)   // 27136 ull
#define SMEM_BYTES (SMEM_ULL * 8)     // 217088 B

__device__ __align__(16) float2 g_packed[NPACK];
__device__ float g_buf0[BV * CHN * HWSZ];
__device__ float g_buf1[BV * CHN * HWSZ];

// ---- packed f32x2 helpers --------------------------------------------------
__device__ __forceinline__ ull pk2(float a, float b) {
    ull r;
    asm("mov.b64 %0, {%1, %2};" : "=l"(r)
        : "r"(__float_as_uint(a)), "r"(__float_as_uint(b)));
    return r;
}
__device__ __forceinline__ void upk2(ull v, float& a, float& b) {
    unsigned int lo, hi;
    asm("mov.b64 {%0, %1}, %2;" : "=r"(lo), "=r"(hi) : "l"(v));
    a = __uint_as_float(lo);
    b = __uint_as_float(hi);
}
__device__ __forceinline__ ull f2fma(ull a, ull b, ull c) {
    ull d;
    asm("fma.rn.f32x2 %0, %1, %2, %3;" : "=l"(d) : "l"(a), "l"(b), "l"(c));
    return d;
}
__device__ __forceinline__ ull f2add(ull a, ull b) {
    ull d;
    asm("add.rn.f32x2 %0, %1, %2;" : "=l"(d) : "l"(a), "l"(b));
    return d;
}
__device__ __forceinline__ ull f2relu(ull a) {
    float x, y;
    upk2(a, x, y);
    return pk2(fmaxf(x, 0.0f), fmaxf(y, 0.0f));
}

// ---- weight packing kernel (tiny, once) ------------------------------------
__global__ void nca_pack(const float* __restrict__ wp, const float* __restrict__ w1,
                         const float* __restrict__ b1, const float* __restrict__ w2,
                         const float* __restrict__ b2, const float* __restrict__ w3) {
    int i = blockIdx.x * blockDim.x + threadIdx.x;
    if (i >= NPACK) return;
    float lo, hi;
    if (i < OFF_W1) {                       // conv weights (OIHW, O=48,I=16,3x3)
        int oc2 = i % 24;
        int r   = i / 24;
        int ic  = r / 9;
        int t   = r % 9;
        lo = wp[((2 * oc2) * 16 + ic) * 9 + t];
        hi = wp[((2 * oc2 + 1) * 16 + ic) * 9 + t];
    } else if (i < OFF_W2) {                // w1 [128,48]
        int j  = i - OFF_W1;
        int o2 = j % 64;
        int c  = j / 64;
        lo = w1[(2 * o2) * 48 + c];
        hi = w1[(2 * o2 + 1) * 48 + c];
    } else if (i < OFF_W3) {                // w2 [128,128]
        int j  = i - OFF_W2;
        int o2 = j % 64;
        int c  = j / 64;
        lo = w2[(2 * o2) * 128 + c];
        hi = w2[(2 * o2 + 1) * 128 + c];
    } else if (i < OFF_B1) {                // w3 [16,128] -> [h2ch][dx_pair]
        int j  = i - OFF_W3;
        int k2 = j % 8;
        int o  = j / 8;
        lo = w3[(2 * k2) * 128 + o];
        hi = w3[(2 * k2 + 1) * 128 + o];
    } else if (i < OFF_B2) {                // b1 [128]
        int j = i - OFF_B1;
        lo = b1[2 * j];
        hi = b1[2 * j + 1];
    } else {                                // b2 [128]
        int j = i - OFF_B2;
        lo = b2[2 * j];
        hi = b2[2 * j + 1];
    }
    g_packed[i] = make_float2(lo, hi);
}

// ---- fused CA step (eighth-split x 4 pixels/thread, unrolled k-loops) ------
// src_sel: 0=external input, 1=g_buf0, 2=g_buf1
// dst_sel: 1=g_buf0, 2=g_buf1, 3=external output
__global__ __launch_bounds__(NTHR, 1)
void nca_step(const float* __restrict__ src_ext, float* __restrict__ dst_ext,
              int src_sel, int dst_sel) {
    extern __shared__ ull sw[];

    int tid = threadIdx.x;
    int e   = tid >> 5;           // eighth (warp id): owns 1/8 of channels
    int s   = tid & 31;           // pixel slot

    // stage packed weights into SMEM
    {
        const float4* gp = (const float4*)g_packed;
        float4*       sp = (float4*)sw;
        for (int i = tid; i < NPACK / 2; i += NTHR) sp[i] = gp[i];
    }
    __syncthreads();

    const ull* wp2 = sw + OFF_WP;
    const ull* w1p = sw + OFF_W1;
    const ull* w2p = sw + OFF_W2;
    const ull* w3p = sw + OFF_W3;

    const float* src = (src_sel == 0) ? src_ext : ((src_sel == 1) ? g_buf0 : g_buf1);
    float*       dst = (dst_sel == 3) ? dst_ext : ((dst_sel == 1) ? g_buf0 : g_buf1);

    // 4 pixels/thread: CTA pixels [blockIdx*128, +128); mine: s+32k
    int py[4], px[4];
    const float* pxb[4];
    #pragma unroll
    for (int k = 0; k < 4; k++) {
        int idx = blockIdx.x * PIXPB + s + 32 * k;
        int b   = idx / HWSZ;
        int rm  = idx - b * HWSZ;
        py[k]   = rm / WW;
        px[k]   = rm - py[k] * WW;
        pxb[k]  = src + b * CHN * HWSZ;
    }

    // ---- 3x3 perception conv: my 6 p-ch = 3 pairs x 4 pix ----
    {
        ull p2[12];
        #pragma unroll
        for (int i = 0; i < 12; i++) p2[i] = 0ull;

        #pragma unroll 2
        for (int ic = 0; ic < CHN; ic++) {
            #pragma unroll
            for (int t = 0; t < 9; t++) {
                int dy = t / 3 - 1, dxo = t % 3 - 1;
                float v[4];
                #pragma unroll
                for (int k = 0; k < 4; k++) {
                    int yy = py[k] + dy, xx = px[k] + dxo;
                    bool ok = ((unsigned)yy < HH) && ((unsigned)xx < WW);
                    v[k] = ok ? __ldg(pxb[k] + ic * HWSZ + yy * WW + xx) : 0.0f;
                }
                ull w0 = wp2[(ic * 9 + t) * 24 + 3 * e + 0];
                ull w1v = wp2[(ic * 9 + t) * 24 + 3 * e + 1];
                ull w2v = wp2[(ic * 9 + t) * 24 + 3 * e + 2];
                #pragma unroll
                for (int k = 0; k < 4; k++) {
                    ull vv = pk2(v[k], v[k]);
                    p2[0 + k]  = f2fma(w0,  vv, p2[0 + k]);
                    p2[4 + k]  = f2fma(w1v, vv, p2[4 + k]);
                    p2[8 + k]  = f2fma(w2v, vv, p2[8 + k]);
                }
            }
        }
        #pragma unroll
        for (int j = 0; j < 3; j++)
            #pragma unroll
            for (int k = 0; k < 4; k++)
                sw[XCH_P + (3 * e + j) * PIXPB + s + 32 * k] = p2[j * 4 + k];
    }
    __syncthreads();

    // ---- h1 = relu(W1 p + b1): my 8 pairs x 4 pix -> SMEM ----
    {
        ull h1[32];
        #pragma unroll
        for (int j = 0; j < 8; j++) {
            ull bj = sw[OFF_B1 + 8 * e + j];
            #pragma unroll
            for (int k = 0; k < 4; k++) h1[j * 4 + k] = bj;
        }
        #pragma unroll 2
        for (int c2 = 0; c2 < 24; c2++) {
            float fa[4], fb[4];
            #pragma unroll
            for (int k = 0; k < 4; k++) {
                ull pp = sw[XCH_P + c2 * PIXPB + s + 32 * k];
                upk2(pp, fa[k], fb[k]);
            }
            {
                const ulonglong2* W = (const ulonglong2*)(w1p + (2 * c2) * 64 + 8 * e);
                ulonglong2 t0 = W[0], t1 = W[1], t2 = W[2], t3 = W[3];
                #pragma unroll
                for (int k = 0; k < 4; k++) {
                    ull ua = pk2(fa[k], fa[k]);
                    h1[0  + k] = f2fma(t0.x, ua, h1[0  + k]);
                    h1[4  + k] = f2fma(t0.y, ua, h1[4  + k]);
                    h1[8  + k] = f2fma(t1.x, ua, h1[8  + k]);
                    h1[12 + k] = f2fma(t1.y, ua, h1[12 + k]);
                    h1[16 + k] = f2fma(t2.x, ua, h1[16 + k]);
                    h1[20 + k] = f2fma(t2.y, ua, h1[20 + k]);
                    h1[24 + k] = f2fma(t3.x, ua, h1[24 + k]);
                    h1[28 + k] = f2fma(t3.y, ua, h1[28 + k]);
                }
            }
            {
                const ulonglong2* W = (const ulonglong2*)(w1p + (2 * c2 + 1) * 64 + 8 * e);
                ulonglong2 t0 = W[0], t1 = W[1], t2 = W[2], t3 = W[3];
                #pragma unroll
                for (int k = 0; k < 4; k++) {
                    ull ub = pk2(fb[k], fb[k]);
                    h1[0  + k] = f2fma(t0.x, ub, h1[0  + k]);
                    h1[4  + k] = f2fma(t0.y, ub, h1[4  + k]);
                    h1[8  + k] = f2fma(t1.x, ub, h1[8  + k]);
                    h1[12 + k] = f2fma(t1.y, ub, h1[12 + k]);
                    h1[16 + k] = f2fma(t2.x, ub, h1[16 + k]);
                    h1[20 + k] = f2fma(t2.y, ub, h1[20 + k]);
                    h1[24 + k] = f2fma(t3.x, ub, h1[24 + k]);
                    h1[28 + k] = f2fma(t3.y, ub, h1[28 + k]);
                }
            }
        }
        #pragma unroll
        for (int j = 0; j < 8; j++)
            #pragma unroll
            for (int k = 0; k < 4; k++)
                sw[XCH_H1 + (8 * e + j) * PIXPB + s + 32 * k] = f2relu(h1[j * 4 + k]);
    }
    __syncthreads();

    // ---- h2 = relu(W2 h1 + b2): my 8 pairs x 4 pix in ONE round ----
    ull acc[32];
    #pragma unroll
    for (int j = 0; j < 8; j++) {
        ull bj = sw[OFF_B2 + 8 * e + j];
        #pragma unroll
        for (int k = 0; k < 4; k++) acc[j * 4 + k] = bj;
    }
    #pragma unroll 2
    for (int c2 = 0; c2 < 64; c2++) {
        float fa[4], fb[4];
        #pragma unroll
        for (int k = 0; k < 4; k++) {
            ull hh = sw[XCH_H1 + c2 * PIXPB + s + 32 * k];
            upk2(hh, fa[k], fb[k]);
        }
        {
            const ulonglong2* W = (const ulonglong2*)(w2p + (2 * c2) * 64 + 8 * e);
            ulonglong2 t0 = W[0], t1 = W[1], t2 = W[2], t3 = W[3];
            #pragma unroll
            for (int k = 0; k < 4; k++) {
                ull ua = pk2(fa[k], fa[k]);
                acc[0  + k] = f2fma(t0.x, ua, acc[0  + k]);
                acc[4  + k] = f2fma(t0.y, ua, acc[4  + k]);
                acc[8  + k] = f2fma(t1.x, ua, acc[8  + k]);
                acc[12 + k] = f2fma(t1.y, ua, acc[12 + k]);
                acc[16 + k] = f2fma(t2.x, ua, acc[16 + k]);
                acc[20 + k] = f2fma(t2.y, ua, acc[20 + k]);
                acc[24 + k] = f2fma(t3.x, ua, acc[24 + k]);
                acc[28 + k] = f2fma(t3.y, ua, acc[28 + k]);
            }
        }
        {
            const ulonglong2* W = (const ulonglong2*)(w2p + (2 * c2 + 1) * 64 + 8 * e);
            ulonglong2 t0 = W[0], t1 = W[1], t2 = W[2], t3 = W[3];
            #pragma unroll
            for (int k = 0; k < 4; k++) {
                ull ub = pk2(fb[k], fb[k]);
                acc[0  + k] = f2fma(t0.x, ub, acc[0  + k]);
                acc[4  + k] = f2fma(t0.y, ub, acc[4  + k]);
                acc[8  + k] = f2fma(t1.x, ub, acc[8  + k]);
                acc[12 + k] = f2fma(t1.y, ub, acc[12 + k]);
                acc[16 + k] = f2fma(t2.x, ub, acc[16 + k]);
                acc[20 + k] = f2fma(t2.y, ub, acc[20 + k]);
                acc[24 + k] = f2fma(t3.x, ub, acc[24 + k]);
                acc[28 + k] = f2fma(t3.y, ub, acc[28 + k]);
            }
        }
    }

    // ---- relu(h2) -> dx += W3 h2 (my 16 h2-ch), then 8-way reduce ----
    ull dx2[32];
    #pragma unroll
    for (int i = 0; i < 32; i++) dx2[i] = 0ull;

    #pragma unroll
    for (int j = 0; j < 8; j++) {
        int g0 = 2 * (8 * e + j);
        const ulonglong2* W30 = (const ulonglong2*)(w3p + g0 * 8);
        const ulonglong2* W31 = (const ulonglong2*)(w3p + (g0 + 1) * 8);
        ull w30[8], w31[8];
        #pragma unroll
        for (int m = 0; m < 4; m++) { ulonglong2 t2 = W30[m]; w30[2*m] = t2.x; w30[2*m+1] = t2.y; }
        #pragma unroll
        for (int m = 0; m < 4; m++) { ulonglong2 t2 = W31[m]; w31[2*m] = t2.x; w31[2*m+1] = t2.y; }
        #pragma unroll
        for (int k = 0; k < 4; k++) {
            float u, vv;
            upk2(acc[j * 4 + k], u, vv);
            u  = fmaxf(u, 0.0f);
            vv = fmaxf(vv, 0.0f);
            ull uu = pk2(u, u), vv2 = pk2(vv, vv);
            #pragma unroll
            for (int m = 0; m < 8; m++) dx2[m * 4 + k] = f2fma(w30[m], uu, dx2[m * 4 + k]);
            #pragma unroll
            for (int m = 0; m < 8; m++) dx2[m * 4 + k] = f2fma(w31[m], vv2, dx2[m * 4 + k]);
        }
    }

    // ---- 8-way dx reduce via SMEM (reuse h1 region), residual+clamp+store --
    __syncthreads();   // all h1 reads done; safe to overwrite region
    #pragma unroll
    for (int m = 0; m < 8; m++)
        #pragma unroll
        for (int k = 0; k < 4; k++)
            sw[XCH_H1 + (e * 8 + m) * PIXPB + s + 32 * k] = dx2[m * 4 + k];
    __syncthreads();

    #pragma unroll
    for (int c = 0; c < 4; c++) {
        int cell = tid + NTHR * c;        // 0..1023 = [dx pair j(8)] x [pix(128)]
        int j    = cell >> 7;
        int pxl  = cell & 127;
        ull sum  = sw[XCH_H1 + j * PIXPB + pxl];
        #pragma unroll
        for (int eo = 1; eo < 8; eo++)
            sum = f2add(sum, sw[XCH_H1 + (eo * 8 + j) * PIXPB + pxl]);
        float d0, d1;
        upk2(sum, d0, d1);
        int gidx = blockIdx.x * PIXPB + pxl;
        int b2   = gidx / HWSZ;
        int rr   = gidx - b2 * HWSZ;
        const float* xbb = src + b2 * CHN * HWSZ;
        float*       dbb = dst + b2 * CHN * HWSZ;
        int c0 = 2 * j;
        float x0 = __ldg(xbb + c0 * HWSZ + rr);
        float x1 = __ldg(xbb + (c0 + 1) * HWSZ + rr);
        dbb[c0 * HWSZ + rr]       = fminf(fmaxf(x0 + d0, 0.0f), 1.0f);
        dbb[(c0 + 1) * HWSZ + rr] = fminf(fmaxf(x1 + d1, 0.0f), 1.0f);
    }
}

// ---------------------------------------------------------------------------
extern "C" void kernel_launch(void* const* d_in, const int* in_sizes, int n_in,
                              void* d_out, int out_size) {
    const float* x  = (const float*)d_in[0];
    const float* wp = (const float*)d_in[1];
    const float* w1 = (const float*)d_in[2];
    const float* b1 = (const float*)d_in[3];
    const float* w2 = (const float*)d_in[4];
    const float* b2 = (const float*)d_in[5];
    const float* w3 = (const float*)d_in[6];
    float* out = (float*)d_out;

    cudaFuncSetAttribute(nca_step, cudaFuncAttributeMaxDynamicSharedMemorySize,
                         SMEM_BYTES);

    nca_pack<<<(NPACK + 255) / 256, 256>>>(wp, w1, b1, w2, b2, w3);

    for (int s = 0; s < NSTEPS; s++) {
        int ssel = (s == 0) ? 0 : (((s - 1) & 1) ? 2 : 1);
        int dsel = (s == NSTEPS - 1) ? 3 : ((s & 1) ? 2 : 1);
        nca_step<<<NBLK, NTHR, SMEM_BYTES>>>(x, out, ssel, dsel);
    }
}

// round 14
// speedup vs baseline: 1.6292x; 1.0517x over previous
#include <cuda_runtime.h>
#include <cstdint>

// ---------------------------------------------------------------------------
// NeuralCA: 40 steps of  x = clip(x + MLP(conv3x3(x)), 0, 1)
// Eighth-split x 4 pixels/thread; 1-round w2 (8 output-pairs/thread).
// Unroll w1/w2 k-loops x4 (deeper software pipelining of LDS under FFMA2
// streams) + direct float LDS.32 activation reads (no upk2 MOVs).
// 256 thr/CTA = 128 pixels, 1568 blocks, weights packed f32x2 in SMEM.
// ---------------------------------------------------------------------------

#define BV     4
#define CHN    16
#define HH     224
#define WW     224
#define HWSZ   (HH * WW)
#define NSTEPS 40
#define NPIX   (BV * HWSZ)            // 200704
#define NTHR   256
#define PIXPB  128
#define NBLK   (NPIX / PIXPB)         // 1568

typedef unsigned long long ull;

// packed-weight layout (float2 units == ull slots)
#define OFF_WP 0
#define N_WP   (16 * 9 * 24)          // conv: [ic][tap][oc_pair]   = 3456
#define OFF_W1 (OFF_WP + N_WP)        // 3456
#define N_W1   (48 * 64)              // w1:   [c][o_pair]          = 3072
#define OFF_W2 (OFF_W1 + N_W1)        // 6528
#define N_W2   (128 * 64)             // w2:   [c][o_pair]          = 8192
#define OFF_W3 (OFF_W2 + N_W2)        // 14720
#define N_W3   (128 * 8)              // w3:   [h2ch][dx_pair]      = 1024
#define OFF_B1 (OFF_W3 + N_W3)        // 15744  (64 pairs)
#define OFF_B2 (OFF_B1 + 64)          // 15808  (64 pairs)
#define NPACK  (OFF_B2 + 64)          // 15872 ull = 126976 bytes

// SMEM activation regions (ull units)
#define XCH_P   NPACK                 // p:  [24 pair-rows][128 pix] = 3072
#define XCH_P_N (24 * PIXPB)
#define XCH_H1  (XCH_P + XCH_P_N)     // h1: [64 pair-rows][128 pix] = 8192
#define XCH_H1N (64 * PIXPB)          // (reused for dx partials [8e][8][128])
#define SMEM_ULL (XCH_H1 + XCH_H1N)   // 27136 ull
#define SMEM_BYTES (SMEM_ULL * 8)     // 217088 B

__device__ __align__(16) float2 g_packed[NPACK];
__device__ float g_buf0[BV * CHN * HWSZ];
__device__ float g_buf1[BV * CHN * HWSZ];

// ---- packed f32x2 helpers --------------------------------------------------
__device__ __forceinline__ ull pk2(float a, float b) {
    ull r;
    asm("mov.b64 %0, {%1, %2};" : "=l"(r)
        : "r"(__float_as_uint(a)), "r"(__float_as_uint(b)));
    return r;
}
__device__ __forceinline__ void upk2(ull v, float& a, float& b) {
    unsigned int lo, hi;
    asm("mov.b64 {%0, %1}, %2;" : "=r"(lo), "=r"(hi) : "l"(v));
    a = __uint_as_float(lo);
    b = __uint_as_float(hi);
}
__device__ __forceinline__ ull f2fma(ull a, ull b, ull c) {
    ull d;
    asm("fma.rn.f32x2 %0, %1, %2, %3;" : "=l"(d) : "l"(a), "l"(b), "l"(c));
    return d;
}
__device__ __forceinline__ ull f2add(ull a, ull b) {
    ull d;
    asm("add.rn.f32x2 %0, %1, %2;" : "=l"(d) : "l"(a), "l"(b));
    return d;
}
__device__ __forceinline__ ull f2relu(ull a) {
    float x, y;
    upk2(a, x, y);
    return pk2(fmaxf(x, 0.0f), fmaxf(y, 0.0f));
}

// ---- weight packing kernel (tiny, once) ------------------------------------
__global__ void nca_pack(const float* __restrict__ wp, const float* __restrict__ w1,
                         const float* __restrict__ b1, const float* __restrict__ w2,
                         const float* __restrict__ b2, const float* __restrict__ w3) {
    int i = blockIdx.x * blockDim.x + threadIdx.x;
    if (i >= NPACK) return;
    float lo, hi;
    if (i < OFF_W1) {                       // conv weights (OIHW, O=48,I=16,3x3)
        int oc2 = i % 24;
        int r   = i / 24;
        int ic  = r / 9;
        int t   = r % 9;
        lo = wp[((2 * oc2) * 16 + ic) * 9 + t];
        hi = wp[((2 * oc2 + 1) * 16 + ic) * 9 + t];
    } else if (i < OFF_W2) {                // w1 [128,48]
        int j  = i - OFF_W1;
        int o2 = j % 64;
        int c  = j / 64;
        lo = w1[(2 * o2) * 48 + c];
        hi = w1[(2 * o2 + 1) * 48 + c];
    } else if (i < OFF_W3) {                // w2 [128,128]
        int j  = i - OFF_W2;
        int o2 = j % 64;
        int c  = j / 64;
        lo = w2[(2 * o2) * 128 + c];
        hi = w2[(2 * o2 + 1) * 128 + c];
    } else if (i < OFF_B1) {                // w3 [16,128] -> [h2ch][dx_pair]
        int j  = i - OFF_W3;
        int k2 = j % 8;
        int o  = j / 8;
        lo = w3[(2 * k2) * 128 + o];
        hi = w3[(2 * k2 + 1) * 128 + o];
    } else if (i < OFF_B2) {                // b1 [128]
        int j = i - OFF_B1;
        lo = b1[2 * j];
        hi = b1[2 * j + 1];
    } else {                                // b2 [128]
        int j = i - OFF_B2;
        lo = b2[2 * j];
        hi = b2[2 * j + 1];
    }
    g_packed[i] = make_float2(lo, hi);
}

// ---- fused CA step (eighth-split x 4 pixels/thread, unroll-4 k-loops) ------
// src_sel: 0=external input, 1=g_buf0, 2=g_buf1
// dst_sel: 1=g_buf0, 2=g_buf1, 3=external output
__global__ __launch_bounds__(NTHR, 1)
void nca_step(const float* __restrict__ src_ext, float* __restrict__ dst_ext,
              int src_sel, int dst_sel) {
    extern __shared__ ull sw[];
    const float* swf = (const float*)sw;   // scalar view of SMEM

    int tid = threadIdx.x;
    int e   = tid >> 5;           // eighth (warp id): owns 1/8 of channels
    int s   = tid & 31;           // pixel slot

    // stage packed weights into SMEM
    {
        const float4* gp = (const float4*)g_packed;
        float4*       sp = (float4*)sw;
        for (int i = tid; i < NPACK / 2; i += NTHR) sp[i] = gp[i];
    }
    __syncthreads();

    const ull* wp2 = sw + OFF_WP;
    const ull* w1p = sw + OFF_W1;
    const ull* w2p = sw + OFF_W2;
    const ull* w3p = sw + OFF_W3;

    const float* src = (src_sel == 0) ? src_ext : ((src_sel == 1) ? g_buf0 : g_buf1);
    float*       dst = (dst_sel == 3) ? dst_ext : ((dst_sel == 1) ? g_buf0 : g_buf1);

    // 4 pixels/thread: CTA pixels [blockIdx*128, +128); mine: s+32k
    int py[4], px[4];
    const float* pxb[4];
    #pragma unroll
    for (int k = 0; k < 4; k++) {
        int idx = blockIdx.x * PIXPB + s + 32 * k;
        int b   = idx / HWSZ;
        int rm  = idx - b * HWSZ;
        py[k]   = rm / WW;
        px[k]   = rm - py[k] * WW;
        pxb[k]  = src + b * CHN * HWSZ;
    }

    // ---- 3x3 perception conv: my 6 p-ch = 3 pairs x 4 pix ----
    {
        ull p2[12];
        #pragma unroll
        for (int i = 0; i < 12; i++) p2[i] = 0ull;

        #pragma unroll 2
        for (int ic = 0; ic < CHN; ic++) {
            #pragma unroll
            for (int t = 0; t < 9; t++) {
                int dy = t / 3 - 1, dxo = t % 3 - 1;
                float v[4];
                #pragma unroll
                for (int k = 0; k < 4; k++) {
                    int yy = py[k] + dy, xx = px[k] + dxo;
                    bool ok = ((unsigned)yy < HH) && ((unsigned)xx < WW);
                    v[k] = ok ? __ldg(pxb[k] + ic * HWSZ + yy * WW + xx) : 0.0f;
                }
                ull w0 = wp2[(ic * 9 + t) * 24 + 3 * e + 0];
                ull w1v = wp2[(ic * 9 + t) * 24 + 3 * e + 1];
                ull w2v = wp2[(ic * 9 + t) * 24 + 3 * e + 2];
                #pragma unroll
                for (int k = 0; k < 4; k++) {
                    ull vv = pk2(v[k], v[k]);
                    p2[0 + k]  = f2fma(w0,  vv, p2[0 + k]);
                    p2[4 + k]  = f2fma(w1v, vv, p2[4 + k]);
                    p2[8 + k]  = f2fma(w2v, vv, p2[8 + k]);
                }
            }
        }
        #pragma unroll
        for (int j = 0; j < 3; j++)
            #pragma unroll
            for (int k = 0; k < 4; k++)
                sw[XCH_P + (3 * e + j) * PIXPB + s + 32 * k] = p2[j * 4 + k];
    }
    __syncthreads();

    // ---- h1 = relu(W1 p + b1): my 8 pairs x 4 pix -> SMEM ----
    {
        ull h1[32];
        #pragma unroll
        for (int j = 0; j < 8; j++) {
            ull bj = sw[OFF_B1 + 8 * e + j];
            #pragma unroll
            for (int k = 0; k < 4; k++) h1[j * 4 + k] = bj;
        }
        #pragma unroll 4
        for (int c2 = 0; c2 < 24; c2++) {
            float fa[4], fb[4];
            #pragma unroll
            for (int k = 0; k < 4; k++) {
                int base = 2 * (XCH_P + c2 * PIXPB + s + 32 * k);
                fa[k] = swf[base];
                fb[k] = swf[base + 1];
            }
            {
                const ulonglong2* W = (const ulonglong2*)(w1p + (2 * c2) * 64 + 8 * e);
                ulonglong2 t0 = W[0], t1 = W[1], t2 = W[2], t3 = W[3];
                #pragma unroll
                for (int k = 0; k < 4; k++) {
                    ull ua = pk2(fa[k], fa[k]);
                    h1[0  + k] = f2fma(t0.x, ua, h1[0  + k]);
                    h1[4  + k] = f2fma(t0.y, ua, h1[4  + k]);
                    h1[8  + k] = f2fma(t1.x, ua, h1[8  + k]);
                    h1[12 + k] = f2fma(t1.y, ua, h1[12 + k]);
                    h1[16 + k] = f2fma(t2.x, ua, h1[16 + k]);
                    h1[20 + k] = f2fma(t2.y, ua, h1[20 + k]);
                    h1[24 + k] = f2fma(t3.x, ua, h1[24 + k]);
                    h1[28 + k] = f2fma(t3.y, ua, h1[28 + k]);
                }
            }
            {
                const ulonglong2* W = (const ulonglong2*)(w1p + (2 * c2 + 1) * 64 + 8 * e);
                ulonglong2 t0 = W[0], t1 = W[1], t2 = W[2], t3 = W[3];
                #pragma unroll
                for (int k = 0; k < 4; k++) {
                    ull ub = pk2(fb[k], fb[k]);
                    h1[0  + k] = f2fma(t0.x, ub, h1[0  + k]);
                    h1[4  + k] = f2fma(t0.y, ub, h1[4  + k]);
                    h1[8  + k] = f2fma(t1.x, ub, h1[8  + k]);
                    h1[12 + k] = f2fma(t1.y, ub, h1[12 + k]);
                    h1[16 + k] = f2fma(t2.x, ub, h1[16 + k]);
                    h1[20 + k] = f2fma(t2.y, ub, h1[20 + k]);
                    h1[24 + k] = f2fma(t3.x, ub, h1[24 + k]);
                    h1[28 + k] = f2fma(t3.y, ub, h1[28 + k]);
                }
            }
        }
        #pragma unroll
        for (int j = 0; j < 8; j++)
            #pragma unroll
            for (int k = 0; k < 4; k++)
                sw[XCH_H1 + (8 * e + j) * PIXPB + s + 32 * k] = f2relu(h1[j * 4 + k]);
    }
    __syncthreads();

    // ---- h2 = relu(W2 h1 + b2): my 8 pairs x 4 pix in ONE round ----
    ull acc[32];
    #pragma unroll
    for (int j = 0; j < 8; j++) {
        ull bj = sw[OFF_B2 + 8 * e + j];
        #pragma unroll
        for (int k = 0; k < 4; k++) acc[j * 4 + k] = bj;
    }
    #pragma unroll 4
    for (int c2 = 0; c2 < 64; c2++) {
        float fa[4], fb[4];
        #pragma unroll
        for (int k = 0; k < 4; k++) {
            int base = 2 * (XCH_H1 + c2 * PIXPB + s + 32 * k);
            fa[k] = swf[base];
            fb[k] = swf[base + 1];
        }
        {
            const ulonglong2* W = (const ulonglong2*)(w2p + (2 * c2) * 64 + 8 * e);
            ulonglong2 t0 = W[0], t1 = W[1], t2 = W[2], t3 = W[3];
            #pragma unroll
            for (int k = 0; k < 4; k++) {
                ull ua = pk2(fa[k], fa[k]);
                acc[0  + k] = f2fma(t0.x, ua, acc[0  + k]);
                acc[4  + k] = f2fma(t0.y, ua, acc[4  + k]);
                acc[8  + k] = f2fma(t1.x, ua, acc[8  + k]);
                acc[12 + k] = f2fma(t1.y, ua, acc[12 + k]);
                acc[16 + k] = f2fma(t2.x, ua, acc[16 + k]);
                acc[20 + k] = f2fma(t2.y, ua, acc[20 + k]);
                acc[24 + k] = f2fma(t3.x, ua, acc[24 + k]);
                acc[28 + k] = f2fma(t3.y, ua, acc[28 + k]);
            }
        }
        {
            const ulonglong2* W = (const ulonglong2*)(w2p + (2 * c2 + 1) * 64 + 8 * e);
            ulonglong2 t0 = W[0], t1 = W[1], t2 = W[2], t3 = W[3];
            #pragma unroll
            for (int k = 0; k < 4; k++) {
                ull ub = pk2(fb[k], fb[k]);
                acc[0  + k] = f2fma(t0.x, ub, acc[0  + k]);
                acc[4  + k] = f2fma(t0.y, ub, acc[4  + k]);
                acc[8  + k] = f2fma(t1.x, ub, acc[8  + k]);
                acc[12 + k] = f2fma(t1.y, ub, acc[12 + k]);
                acc[16 + k] = f2fma(t2.x, ub, acc[16 + k]);
                acc[20 + k] = f2fma(t2.y, ub, acc[20 + k]);
                acc[24 + k] = f2fma(t3.x, ub, acc[24 + k]);
                acc[28 + k] = f2fma(t3.y, ub, acc[28 + k]);
            }
        }
    }

    // ---- relu(h2) -> dx += W3 h2 (my 16 h2-ch), then 8-way reduce ----
    ull dx2[32];
    #pragma unroll
    for (int i = 0; i < 32; i++) dx2[i] = 0ull;

    #pragma unroll
    for (int j = 0; j < 8; j++) {
        int g0 = 2 * (8 * e + j);
        const ulonglong2* W30 = (const ulonglong2*)(w3p + g0 * 8);
        const ulonglong2* W31 = (const ulonglong2*)(w3p + (g0 + 1) * 8);
        ull w30[8], w31[8];
        #pragma unroll
        for (int m = 0; m < 4; m++) { ulonglong2 t2 = W30[m]; w30[2*m] = t2.x; w30[2*m+1] = t2.y; }
        #pragma unroll
        for (int m = 0; m < 4; m++) { ulonglong2 t2 = W31[m]; w31[2*m] = t2.x; w31[2*m+1] = t2.y; }
        #pragma unroll
        for (int k = 0; k < 4; k++) {
            float u, vv;
            upk2(acc[j * 4 + k], u, vv);
            u  = fmaxf(u, 0.0f);
            vv = fmaxf(vv, 0.0f);
            ull uu = pk2(u, u), vv2 = pk2(vv, vv);
            #pragma unroll
            for (int m = 0; m < 8; m++) dx2[m * 4 + k] = f2fma(w30[m], uu, dx2[m * 4 + k]);
            #pragma unroll
            for (int m = 0; m < 8; m++) dx2[m * 4 + k] = f2fma(w31[m], vv2, dx2[m * 4 + k]);
        }
    }

    // ---- 8-way dx reduce via SMEM (reuse h1 region), residual+clamp+store --
    __syncthreads();   // all h1 reads done; safe to overwrite region
    #pragma unroll
    for (int m = 0; m < 8; m++)
        #pragma unroll
        for (int k = 0; k < 4; k++)
            sw[XCH_H1 + (e * 8 + m) * PIXPB + s + 32 * k] = dx2[m * 4 + k];
    __syncthreads();

    #pragma unroll
    for (int c = 0; c < 4; c++) {
        int cell = tid + NTHR * c;        // 0..1023 = [dx pair j(8)] x [pix(128)]
        int j    = cell >> 7;
        int pxl  = cell & 127;
        ull sum  = sw[XCH_H1 + j * PIXPB + pxl];
        #pragma unroll
        for (int eo = 1; eo < 8; eo++)
            sum = f2add(sum, sw[XCH_H1 + (eo * 8 + j) * PIXPB + pxl]);
        float d0, d1;
        upk2(sum, d0, d1);
        int gidx = blockIdx.x * PIXPB + pxl;
        int b2   = gidx / HWSZ;
        int rr   = gidx - b2 * HWSZ;
        const float* xbb = src + b2 * CHN * HWSZ;
        float*       dbb = dst + b2 * CHN * HWSZ;
        int c0 = 2 * j;
        float x0 = __ldg(xbb + c0 * HWSZ + rr);
        float x1 = __ldg(xbb + (c0 + 1) * HWSZ + rr);
        dbb[c0 * HWSZ + rr]       = fminf(fmaxf(x0 + d0, 0.0f), 1.0f);
        dbb[(c0 + 1) * HWSZ + rr] = fminf(fmaxf(x1 + d1, 0.0f), 1.0f);
    }
}

// ---------------------------------------------------------------------------
extern "C" void kernel_launch(void* const* d_in, const int* in_sizes, int n_in,
                              void* d_out, int out_size) {
    const float* x  = (const float*)d_in[0];
    const float* wp = (const float*)d_in[1];
    const float* w1 = (const float*)d_in[2];
    const float* b1 = (const float*)d_in[3];
    const float* w2 = (const float*)d_in[4];
    const float* b2 = (const float*)d_in[5];
    const float* w3 = (const float*)d_in[6];
    float* out = (float*)d_out;

    cudaFuncSetAttribute(nca_step, cudaFuncAttributeMaxDynamicSharedMemorySize,
                         SMEM_BYTES);

    nca_pack<<<(NPACK + 255) / 256, 256>>>(wp, w1, b1, w2, b2, w3);

    for (int s = 0; s < NSTEPS; s++) {
        int ssel = (s == 0) ? 0 : (((s - 1) & 1) ? 2 : 1);
        int dsel = (s == NSTEPS - 1) ? 3 : ((s & 1) ? 2 : 1);
        nca_step<<<NBLK, NTHR, SMEM_BYTES>>>(x, out, ssel, dsel);
    }
}